// round 4
// baseline (speedup 1.0000x reference)
#include <cuda_runtime.h>
#include <stdint.h>

#define B_ 4
#define V_ 778
#define F_ 1538
#define S_ 320
#define TILE 16
#define NT 128         // threads per block; each thread does 2 pixels (rows 2k,2k+1)
#define NW (NT / 32)

// Per (batch, face): 3 edges x (A, B, C, pad). d = A*px + B*py + C, scaled by
// sgn * inv_len * log2(e) / sigma, so exp2(-d) = exp(-dist/sigma).
__device__ float g_coeffs[B_ * F_ * 12];

__global__ void precompute_kernel(const float* __restrict__ verts,
                                  const int* __restrict__ faces) {
    int idx = blockIdx.x * blockDim.x + threadIdx.x;
    if (idx >= B_ * F_) return;
    int b = idx / F_;
    int f = idx - b * F_;
    int i0 = faces[f * 3 + 0], i1 = faces[f * 3 + 1], i2 = faces[f * 3 + 2];
    const float* vb = verts + b * V_ * 3;
    float x0 = vb[i0 * 3 + 0], y0 = -vb[i0 * 3 + 1];
    float x1 = vb[i1 * 3 + 0], y1 = -vb[i1 * 3 + 1];
    float x2 = vb[i2 * 3 + 0], y2 = -vb[i2 * 3 + 1];
    float area2 = (x1 - x0) * (y2 - y0) - (y1 - y0) * (x2 - x0);
    float sgn = (area2 > 0.f) ? 1.f : ((area2 < 0.f) ? -1.f : 0.f);
    const float INVS = 1.4426950408889634f / 0.01f;  // log2(e)/SIGMA

    float ax[3] = {x0, x1, x2}, ay[3] = {y0, y1, y2};
    float bx[3] = {x1, x2, x0}, by[3] = {y1, y2, y0};
    float* o = g_coeffs + idx * 12;
#pragma unroll
    for (int e = 0; e < 3; e++) {
        float ex = bx[e] - ax[e];
        float ey = by[e] - ay[e];
        float inv_len = 1.0f / (sqrtf(ex * ex + ey * ey) + 1e-8f);
        float k = sgn * inv_len * INVS;
        o[e * 4 + 0] = -k * ey;
        o[e * 4 + 1] = k * ex;
        o[e * 4 + 2] = k * (ey * ax[e] - ex * ay[e]);
        o[e * 4 + 3] = 0.f;
    }
}

__device__ __forceinline__ float ex2f(float x) {
    float r; asm("ex2.approx.ftz.f32 %0, %1;" : "=f"(r) : "f"(x)); return r;
}
__device__ __forceinline__ float rcpf(float x) {
    float r; asm("rcp.approx.ftz.f32 %0, %1;" : "=f"(r) : "f"(x)); return r;
}

__device__ __forceinline__ float pixel_r(float d0, float d1, float d2,
                                         float dmin, float DEEP, float RMIN) {
    // caller guarantees dmin > DEAD
    float mn01 = fminf(d0, d1), mx01 = fmaxf(d0, d1);
    float dmid = fmaxf(fminf(mx01, d2), mn01);
    float r;
    if (dmid > DEEP) {
        if (dmin > DEEP) {
            r = RMIN;                               // fully inside: clipped const
        } else {
            float t = ex2f(-dmin);                  // one relevant edge
            r = fmaxf(t * rcpf(1.0f + t), RMIN);
        }
    } else {
        float t0 = ex2f(-d0);
        float t1 = ex2f(-d1);
        float t2 = ex2f(-d2);
        float sA = t1 + t2;
        float pA = t1 * t2;
        float sp = sA + pA;
        float Q = fmaf(t0, sp, t0 + sp);
        r = Q * rcpf(1.0f + Q);
        r = fminf(fmaxf(r, RMIN), 1.0f);
    }
    return r;
}

__global__ __launch_bounds__(NT) void silhouette_kernel(float* __restrict__ out) {
    __shared__ float4 s_face[NT * 3];   // compacted (e0,e1,e2) per active face
    __shared__ int s_wcnt[NW];
    __shared__ int s_wbase[NW];
    __shared__ int s_total;
    __shared__ int s_deep;

    const int tid = threadIdx.x;
    const int w = tid >> 5;
    const int lane = tid & 31;
    const int b = blockIdx.z;
    const int x0 = blockIdx.x * TILE;
    const int y0 = blockIdx.y * TILE;

    if (tid == 0) s_deep = 0;

    // thresholds in (dist/sigma)*log2(e) units
    const float DEAD = -15.8696454f;   // -11*log2e : skip err <= 1.7e-5 per face
    const float DEEP = 21.6404256f;    //  15*log2e : Q <= 9.2e-7 -> clipped RMIN
    const float STEP = 2.0f / S_;

    const float cx = (x0 + 8.0f) * STEP - 1.0f;   // tile center
    const float cy = (y0 + 8.0f) * STEP - 1.0f;
    const float hx = 7.5f * STEP + 1e-4f;         // half extent + margin
    const float hy = hx;

    // this thread's 2 pixels: same column, rows 2*yp and 2*yp+1
    const int xi = tid & 15;
    const int yp = tid >> 4;                      // 0..7
    const int pxi = x0 + xi;
    const int ry = y0 + 2 * yp;
    const float px = (pxi + 0.5f) * STEP - 1.0f;
    const float py0 = (ry + 0.5f) * STEP - 1.0f;

    const float RMIN = 1.0f - (1.0f - 1e-6f);     // exact fp32 clip residue
    float WA = 1.0f, WB = 1.0f;

    const float* cb = g_coeffs + (size_t)b * F_ * 12;

    for (int base = 0; base < F_; base += NT) {
        // ---- cull: one face per thread ----
        int f = base + tid;
        bool active = false, deep = false;
        float4 e0, e1, e2;
        if (f < F_) {
            const float4* cp = (const float4*)(cb + (size_t)f * 12);
            e0 = __ldg(cp); e1 = __ldg(cp + 1); e2 = __ldg(cp + 2);
            float dc0 = fmaf(e0.x, cx, fmaf(e0.y, cy, e0.z));
            float dc1 = fmaf(e1.x, cx, fmaf(e1.y, cy, e1.z));
            float dc2 = fmaf(e2.x, cx, fmaf(e2.y, cy, e2.z));
            float x0e = fmaf(fabsf(e0.x), hx, fabsf(e0.y) * hy);
            float x1e = fmaf(fabsf(e1.x), hx, fabsf(e1.y) * hy);
            float x2e = fmaf(fabsf(e2.x), hx, fabsf(e2.y) * hy);
            bool dead = (dc0 + x0e < DEAD) || (dc1 + x1e < DEAD) || (dc2 + x2e < DEAD);
            deep = (dc0 - x0e > DEEP) && (dc1 - x1e > DEEP) && (dc2 - x2e > DEEP);
            active = !dead && !deep;
        }
        unsigned balA = __ballot_sync(0xffffffffu, active);
        unsigned balD = __ballot_sync(0xffffffffu, deep);
        if (lane == 0) {
            s_wcnt[w] = __popc(balA);
            if (balD) atomicAdd(&s_deep, __popc(balD));
        }
        __syncthreads();
        if (tid == 0) {   // NW-entry exclusive scan (deterministic order)
            int acc = 0;
#pragma unroll
            for (int i = 0; i < NW; i++) { s_wbase[i] = acc; acc += s_wcnt[i]; }
            s_total = acc;
        }
        __syncthreads();
        if (active) {
            int pos = s_wbase[w] + __popc(balA & ((1u << lane) - 1u));
            s_face[pos * 3 + 0] = e0;
            s_face[pos * 3 + 1] = e1;
            s_face[pos * 3 + 2] = e2;
        }
        __syncthreads();

        // ---- eval: 2 pixels per thread over the compacted face list ----
        const int n = s_total;
#pragma unroll 1
        for (int j = 0; j < n; j++) {
            float4 f0 = s_face[j * 3 + 0];
            float4 f1 = s_face[j * 3 + 1];
            float4 f2 = s_face[j * 3 + 2];
            // row0 distances
            float a0 = fmaf(f0.y, py0, fmaf(f0.x, px, f0.z));
            float a1 = fmaf(f1.y, py0, fmaf(f1.x, px, f1.z));
            float a2 = fmaf(f2.y, py0, fmaf(f2.x, px, f2.z));
            // row1 = row0 + B*STEP (incremental)
            float b0 = fmaf(f0.y, STEP, a0);
            float b1 = fmaf(f1.y, STEP, a1);
            float b2 = fmaf(f2.y, STEP, a2);

            float dminA = fminf(fminf(a0, a1), a2);
            float dminB = fminf(fminf(b0, b1), b2);

            // warp-uniform skip when the whole 16x4 strip is dead for this face
            bool anyLive = (fmaxf(dminA, dminB) > DEAD);
            if (!__ballot_sync(0xffffffffu, anyLive)) continue;

            if (dminA > DEAD) WA *= pixel_r(a0, a1, a2, dminA, DEEP, RMIN);
            if (dminB > DEAD) WB *= pixel_r(b0, b1, b2, dminB, DEEP, RMIN);
        }
        __syncthreads();   // protect s_face before next pass
    }

    // fold in deep (fully-covering) faces: exact clipped constant per face
    int nd = s_deep;
    if (nd >= 8) {
        WA = 0.0f; WB = 0.0f;
    } else {
        for (int i = 0; i < nd; i++) { WA *= RMIN; WB *= RMIN; }
    }

    float* op = out + ((size_t)b * S_ + ry) * S_ + pxi;
    op[0] = 1.0f - WA;
    op[S_] = 1.0f - WB;
}

extern "C" void kernel_launch(void* const* d_in, const int* in_sizes, int n_in,
                              void* d_out, int out_size) {
    const float* verts = (const float*)d_in[0];
    const int* faces = (const int*)d_in[1];
    float* out = (float*)d_out;

    int total = B_ * F_;
    precompute_kernel<<<(total + 255) / 256, 256>>>(verts, faces);

    dim3 grid(S_ / TILE, S_ / TILE, B_);
    silhouette_kernel<<<grid, NT>>>(out);
}

// round 5
// speedup vs baseline: 1.0939x; 1.0939x over previous
#include <cuda_runtime.h>
#include <stdint.h>

#define B_ 4
#define V_ 778
#define F_ 1538
#define S_ 320
#define TX 16          // tile width
#define TY 32          // tile height
#define NT 256         // threads/block; each thread: 2 vertically-adjacent pixels
#define NW (NT / 32)

// Per (batch, face): 3 edges x (A, B, C, pad). d = A*px + B*py + C, scaled by
// sgn * inv_len * log2(e) / sigma, so exp2(-d) = exp(-dist/sigma).
__device__ float g_coeffs[B_ * F_ * 12];

__global__ void precompute_kernel(const float* __restrict__ verts,
                                  const int* __restrict__ faces) {
    int idx = blockIdx.x * blockDim.x + threadIdx.x;
    if (idx >= B_ * F_) return;
    int b = idx / F_;
    int f = idx - b * F_;
    int i0 = faces[f * 3 + 0], i1 = faces[f * 3 + 1], i2 = faces[f * 3 + 2];
    const float* vb = verts + b * V_ * 3;
    float x0 = vb[i0 * 3 + 0], y0 = -vb[i0 * 3 + 1];
    float x1 = vb[i1 * 3 + 0], y1 = -vb[i1 * 3 + 1];
    float x2 = vb[i2 * 3 + 0], y2 = -vb[i2 * 3 + 1];
    float area2 = (x1 - x0) * (y2 - y0) - (y1 - y0) * (x2 - x0);
    float sgn = (area2 > 0.f) ? 1.f : ((area2 < 0.f) ? -1.f : 0.f);
    const float INVS = 1.4426950408889634f / 0.01f;  // log2(e)/SIGMA

    float ax[3] = {x0, x1, x2}, ay[3] = {y0, y1, y2};
    float bx[3] = {x1, x2, x0}, by[3] = {y1, y2, y0};
    float* o = g_coeffs + idx * 12;
#pragma unroll
    for (int e = 0; e < 3; e++) {
        float ex = bx[e] - ax[e];
        float ey = by[e] - ay[e];
        float inv_len = 1.0f / (sqrtf(ex * ex + ey * ey) + 1e-8f);
        float k = sgn * inv_len * INVS;
        o[e * 4 + 0] = -k * ey;
        o[e * 4 + 1] = k * ex;
        o[e * 4 + 2] = k * (ey * ax[e] - ex * ay[e]);
        o[e * 4 + 3] = 0.f;
    }
}

__device__ __forceinline__ float ex2f(float x) {
    float r; asm("ex2.approx.ftz.f32 %0, %1;" : "=f"(r) : "f"(x)); return r;
}
__device__ __forceinline__ float rcpf(float x) {
    float r; asm("rcp.approx.ftz.f32 %0, %1;" : "=f"(r) : "f"(x)); return r;
}

__device__ __forceinline__ float pixel_r(float d0, float d1, float d2,
                                         float dmin, float DEEP, float RMIN) {
    // caller guarantees dmin > DEAD
    float mn01 = fminf(d0, d1), mx01 = fmaxf(d0, d1);
    float dmid = fmaxf(fminf(mx01, d2), mn01);
    float r;
    if (dmid > DEEP) {
        if (dmin > DEEP) {
            r = RMIN;                               // fully inside: clipped const
        } else {
            float t = ex2f(-dmin);                  // one relevant edge
            r = fmaxf(t * rcpf(1.0f + t), RMIN);
        }
    } else {
        float t0 = ex2f(-d0);
        float t1 = ex2f(-d1);
        float t2 = ex2f(-d2);
        float sA = t1 + t2;
        float pA = t1 * t2;
        float sp = sA + pA;
        float Q = fmaf(t0, sp, t0 + sp);
        r = Q * rcpf(1.0f + Q);
        r = fminf(fmaxf(r, RMIN), 1.0f);
    }
    return r;
}

__global__ __launch_bounds__(NT) void silhouette_kernel(float* __restrict__ out) {
    __shared__ float4 s_face[NT * 3];   // compacted (e0,e1,e2) per active face
    __shared__ int s_wcnt[NW];
    __shared__ int s_wbase[NW];
    __shared__ int s_total;
    __shared__ int s_deep;

    const int tid = threadIdx.x;
    const int w = tid >> 5;
    const int lane = tid & 31;
    const int b = blockIdx.z;
    const int x0 = blockIdx.x * TX;
    const int y0 = blockIdx.y * TY;

    if (tid == 0) s_deep = 0;

    // thresholds in (dist/sigma)*log2(e) units
    const float DEAD = -15.8696454f;   // -11*log2e : skip err <= 1.7e-5 per face
    const float DEEP = 21.6404256f;    //  15*log2e : Q <= 9.2e-7 -> clipped RMIN
    const float STEP = 2.0f / S_;

    const float cx = (x0 + 8.0f) * STEP - 1.0f;     // tile center x
    const float cy = (y0 + 16.0f) * STEP - 1.0f;    // tile center y
    const float hx = 7.5f * STEP + 1e-4f;           // half extents + margin
    const float hy = 15.5f * STEP + 1e-4f;

    // this thread's 2 pixels: column xi, rows 2*yp and 2*yp+1
    const int xi = tid & 15;
    const int yp = tid >> 4;                        // 0..15
    const int pxi = x0 + xi;
    const int ry = y0 + 2 * yp;
    const float px = (pxi + 0.5f) * STEP - 1.0f;
    const float py0 = (ry + 0.5f) * STEP - 1.0f;

    const float RMIN = 1.0f - (1.0f - 1e-6f);       // exact fp32 clip residue
    float WA = 1.0f, WB = 1.0f;

    const float* cb = g_coeffs + (size_t)b * F_ * 12;

    for (int base = 0; base < F_; base += NT) {
        // ---- cull: one face per thread ----
        int f = base + tid;
        bool active = false, deep = false;
        float4 e0, e1, e2;
        if (f < F_) {
            const float4* cp = (const float4*)(cb + (size_t)f * 12);
            e0 = __ldg(cp); e1 = __ldg(cp + 1); e2 = __ldg(cp + 2);
            float dc0 = fmaf(e0.x, cx, fmaf(e0.y, cy, e0.z));
            float dc1 = fmaf(e1.x, cx, fmaf(e1.y, cy, e1.z));
            float dc2 = fmaf(e2.x, cx, fmaf(e2.y, cy, e2.z));
            float x0e = fmaf(fabsf(e0.x), hx, fabsf(e0.y) * hy);
            float x1e = fmaf(fabsf(e1.x), hx, fabsf(e1.y) * hy);
            float x2e = fmaf(fabsf(e2.x), hx, fabsf(e2.y) * hy);
            bool dead = (dc0 + x0e < DEAD) || (dc1 + x1e < DEAD) || (dc2 + x2e < DEAD);
            deep = (dc0 - x0e > DEEP) && (dc1 - x1e > DEEP) && (dc2 - x2e > DEEP);
            active = !dead && !deep;
        }
        unsigned balA = __ballot_sync(0xffffffffu, active);
        unsigned balD = __ballot_sync(0xffffffffu, deep);
        if (lane == 0) {
            s_wcnt[w] = __popc(balA);
            if (balD) atomicAdd(&s_deep, __popc(balD));
        }
        __syncthreads();
        if (tid == 0) {   // NW-entry exclusive scan (deterministic order)
            int acc = 0;
#pragma unroll
            for (int i = 0; i < NW; i++) { s_wbase[i] = acc; acc += s_wcnt[i]; }
            s_total = acc;
        }
        __syncthreads();
        if (active) {
            int pos = s_wbase[w] + __popc(balA & ((1u << lane) - 1u));
            s_face[pos * 3 + 0] = e0;
            s_face[pos * 3 + 1] = e1;
            s_face[pos * 3 + 2] = e2;
        }
        __syncthreads();

        // ---- eval: 2 pixels per thread over the compacted face list ----
        const int n = s_total;
        const float4* sp_ = s_face;
#pragma unroll 2
        for (int j = 0; j < n; j++, sp_ += 3) {
            float4 f0 = sp_[0];
            float4 f1 = sp_[1];
            float4 f2 = sp_[2];
            // row0 distances
            float a0 = fmaf(f0.y, py0, fmaf(f0.x, px, f0.z));
            float a1 = fmaf(f1.y, py0, fmaf(f1.x, px, f1.z));
            float a2 = fmaf(f2.y, py0, fmaf(f2.x, px, f2.z));
            // row1 = row0 + B*STEP (incremental)
            float b0 = fmaf(f0.y, STEP, a0);
            float b1 = fmaf(f1.y, STEP, a1);
            float b2 = fmaf(f2.y, STEP, a2);

            float dminA = fminf(fminf(a0, a1), a2);
            float dminB = fminf(fminf(b0, b1), b2);

            if (dminA > DEAD) WA *= pixel_r(a0, a1, a2, dminA, DEEP, RMIN);
            if (dminB > DEAD) WB *= pixel_r(b0, b1, b2, dminB, DEEP, RMIN);
        }
        __syncthreads();   // protect s_face before next pass
    }

    // fold in deep (fully-covering) faces: exact clipped constant per face
    int nd = s_deep;
    if (nd >= 8) {
        WA = 0.0f; WB = 0.0f;
    } else {
        for (int i = 0; i < nd; i++) { WA *= RMIN; WB *= RMIN; }
    }

    float* op = out + ((size_t)b * S_ + ry) * S_ + pxi;
    op[0] = 1.0f - WA;
    op[S_] = 1.0f - WB;
}

extern "C" void kernel_launch(void* const* d_in, const int* in_sizes, int n_in,
                              void* d_out, int out_size) {
    const float* verts = (const float*)d_in[0];
    const int* faces = (const int*)d_in[1];
    float* out = (float*)d_out;

    int total = B_ * F_;
    precompute_kernel<<<(total + 255) / 256, 256>>>(verts, faces);

    dim3 grid(S_ / TX, S_ / TY, B_);
    silhouette_kernel<<<grid, NT>>>(out);
}

// round 6
// speedup vs baseline: 1.6365x; 1.4961x over previous
#include <cuda_runtime.h>
#include <stdint.h>

#define B_ 4
#define V_ 778
#define F_ 1538
#define S_ 320
#define TILE 16
#define NT 256
#define NW (NT / 32)
#define NHALF 2
#define HFACES ((F_ + NHALF - 1) / NHALF)   // 769

// Per (batch, face): 3 edges x (A', B', C', pad) with NEGATED scaled coeffs:
// dn = A'*px + B'*py + C' = -(dist/sigma)*log2(e);  t = exp2(dn) = exp(-dist/sigma).
__device__ float g_coeffs[B_ * F_ * 12];
// partial products per half: [half][b][y][x]
__device__ float g_part[NHALF * B_ * S_ * S_];

__global__ void precompute_kernel(const float* __restrict__ verts,
                                  const int* __restrict__ faces) {
    int idx = blockIdx.x * blockDim.x + threadIdx.x;
    if (idx >= B_ * F_) return;
    int b = idx / F_;
    int f = idx - b * F_;
    int i0 = faces[f * 3 + 0], i1 = faces[f * 3 + 1], i2 = faces[f * 3 + 2];
    const float* vb = verts + b * V_ * 3;
    float x0 = vb[i0 * 3 + 0], y0 = -vb[i0 * 3 + 1];
    float x1 = vb[i1 * 3 + 0], y1 = -vb[i1 * 3 + 1];
    float x2 = vb[i2 * 3 + 0], y2 = -vb[i2 * 3 + 1];
    float area2 = (x1 - x0) * (y2 - y0) - (y1 - y0) * (x2 - x0);
    float sgn = (area2 > 0.f) ? 1.f : ((area2 < 0.f) ? -1.f : 0.f);
    const float INVS = 1.4426950408889634f / 0.01f;  // log2(e)/SIGMA

    float ax[3] = {x0, x1, x2}, ay[3] = {y0, y1, y2};
    float bx[3] = {x1, x2, x0}, by[3] = {y1, y2, y0};
    float* o = g_coeffs + idx * 12;
#pragma unroll
    for (int e = 0; e < 3; e++) {
        float ex = bx[e] - ax[e];
        float ey = by[e] - ay[e];
        float inv_len = 1.0f / (sqrtf(ex * ex + ey * ey) + 1e-8f);
        float k = sgn * inv_len * INVS;
        // negated coefficients
        o[e * 4 + 0] = k * ey;
        o[e * 4 + 1] = -k * ex;
        o[e * 4 + 2] = k * (ex * ay[e] - ey * ax[e]);
        o[e * 4 + 3] = 0.f;
    }
}

__device__ __forceinline__ float ex2f(float x) {
    float r; asm("ex2.approx.ftz.f32 %0, %1;" : "=f"(r) : "f"(x)); return r;
}
__device__ __forceinline__ float rcpf(float x) {
    float r; asm("rcp.approx.ftz.f32 %0, %1;" : "=f"(r) : "f"(x)); return r;
}

__global__ __launch_bounds__(NT) void silhouette_kernel() {
    __shared__ float4 s_face[NT * 3];   // compacted (e0,e1,e2) per active face
    __shared__ int s_wcnt[NW];
    __shared__ int s_wbase[NW];
    __shared__ int s_total;
    __shared__ int s_deep;

    const int tid = threadIdx.x;
    const int w = tid >> 5;
    const int lane = tid & 31;
    const int bz = blockIdx.z;          // b*NHALF + half
    const int b = bz >> 1;
    const int half = bz & 1;
    const int x0 = blockIdx.x * TILE;
    const int y0 = blockIdx.y * TILE;

    if (tid == 0) s_deep = 0;
    __syncthreads();

    // thresholds on dn = -(dist/sigma)*log2(e)
    const float L = 12.262907f;        // 8.5*log2e : live if max(dn) < L
    const float DPN = -21.6404256f;    // -15*log2e : dn < DPN means edge deep
    const float STEP = 2.0f / S_;

    const float cx = (x0 + 8.0f) * STEP - 1.0f;
    const float cy = (y0 + 8.0f) * STEP - 1.0f;
    const float hx = 7.5f * STEP + 1e-4f;
    const float hy = hx;

    const int pxi = x0 + (tid & 15);
    const int pyi = y0 + (tid >> 4);
    const float px = (pxi + 0.5f) * STEP - 1.0f;
    const float py = (pyi + 0.5f) * STEP - 1.0f;

    const float RMIN = 1.0f - (1.0f - 1e-6f);   // exact fp32 clip residue
    float W = 1.0f;

    const float* cb = g_coeffs + (size_t)b * F_ * 12;
    const int fLo = half * HFACES;
    const int fHi = min(fLo + HFACES, F_);

    for (int base = fLo; base < fHi; base += NT) {
        // ---- cull: one face per thread ----
        int f = base + tid;
        bool active = false, deep = false;
        float4 e0, e1, e2;
        if (f < fHi) {
            const float4* cp = (const float4*)(cb + (size_t)f * 12);
            e0 = __ldg(cp); e1 = __ldg(cp + 1); e2 = __ldg(cp + 2);
            float n0 = fmaf(e0.x, cx, fmaf(e0.y, cy, e0.z));
            float n1 = fmaf(e1.x, cx, fmaf(e1.y, cy, e1.z));
            float n2 = fmaf(e2.x, cx, fmaf(e2.y, cy, e2.z));
            float x0e = fmaf(fabsf(e0.x), hx, fabsf(e0.y) * hy);
            float x1e = fmaf(fabsf(e1.x), hx, fabsf(e1.y) * hy);
            float x2e = fmaf(fabsf(e2.x), hx, fabsf(e2.y) * hy);
            // dead: whole tile beyond L on some edge (dn - ext > L)
            bool dead = (n0 - x0e > L) || (n1 - x1e > L) || (n2 - x2e > L);
            // deep: whole tile deep inside all edges (dn + ext < DPN)
            deep = (n0 + x0e < DPN) && (n1 + x1e < DPN) && (n2 + x2e < DPN);
            active = !dead && !deep;
        }
        unsigned balA = __ballot_sync(0xffffffffu, active);
        unsigned balD = __ballot_sync(0xffffffffu, deep);
        if (lane == 0) {
            s_wcnt[w] = __popc(balA);
            if (balD) atomicAdd(&s_deep, __popc(balD));
        }
        __syncthreads();
        if (tid == 0) {   // deterministic exclusive scan
            int acc = 0;
#pragma unroll
            for (int i = 0; i < NW; i++) { s_wbase[i] = acc; acc += s_wcnt[i]; }
            s_total = acc;
        }
        __syncthreads();
        if (active) {
            int pos = s_wbase[w] + __popc(balA & ((1u << lane) - 1u));
            s_face[pos * 3 + 0] = e0;
            s_face[pos * 3 + 1] = e1;
            s_face[pos * 3 + 2] = e2;
        }
        __syncthreads();

        // ---- eval: one pixel per thread over compacted faces ----
        const int n = s_total;
        const float4* sp_ = s_face;
#pragma unroll 2
        for (int j = 0; j < n; j++, sp_ += 3) {
            float4 f0 = sp_[0];
            float4 f1 = sp_[1];
            float4 f2 = sp_[2];
            float dn0 = fmaf(f0.x, px, fmaf(f0.y, py, f0.z));
            float dn1 = fmaf(f1.x, px, fmaf(f1.y, py, f1.z));
            float dn2 = fmaf(f2.x, px, fmaf(f2.y, py, f2.z));
            float mx01 = fmaxf(dn0, dn1);
            float m = fmaxf(mx01, dn2);
            if (m < L) {
                float r;
                if (m < DPN) {
                    r = RMIN;                       // all edges deep: clipped const
                } else {
                    float mn01 = fminf(dn0, dn1);
                    float mid = fmaxf(mn01, fminf(mx01, dn2));
                    if (mid < DPN) {
                        float t = ex2f(m);          // single relevant edge
                        r = fmaxf(t * rcpf(1.0f + t), RMIN);
                    } else {
                        float t0 = ex2f(dn0);
                        float t1 = ex2f(dn1);
                        float t2 = ex2f(dn2);
                        float sA = t1 + t2;
                        float pA = t1 * t2;
                        float sp = sA + pA;
                        float Q = fmaf(t0, sp, t0 + sp);
                        r = fmaxf(Q * rcpf(1.0f + Q), RMIN);
                    }
                }
                W *= r;
            }
        }
        __syncthreads();   // protect s_face
    }

    // fold deep faces of this half: exact clipped constant per face
    int nd = s_deep;
    if (nd >= 8) {
        W = 0.0f;
    } else {
        for (int i = 0; i < nd; i++) W *= RMIN;
    }

    g_part[(((size_t)half * B_ + b) * S_ + pyi) * S_ + pxi] = W;
}

__global__ __launch_bounds__(256) void combine_kernel(float* __restrict__ out) {
    int i = blockIdx.x * blockDim.x + threadIdx.x;
    if (i >= B_ * S_ * S_) return;
    float wa = g_part[i];
    float wb = g_part[B_ * S_ * S_ + i];
    out[i] = 1.0f - wa * wb;
}

extern "C" void kernel_launch(void* const* d_in, const int* in_sizes, int n_in,
                              void* d_out, int out_size) {
    const float* verts = (const float*)d_in[0];
    const int* faces = (const int*)d_in[1];
    float* out = (float*)d_out;

    int total = B_ * F_;
    precompute_kernel<<<(total + 255) / 256, 256>>>(verts, faces);

    dim3 grid(S_ / TILE, S_ / TILE, B_ * NHALF);
    silhouette_kernel<<<grid, NT>>>();

    int npix = B_ * S_ * S_;
    combine_kernel<<<(npix + 255) / 256, 256>>>(out);
}

// round 7
// speedup vs baseline: 1.9811x; 1.2106x over previous
#include <cuda_runtime.h>
#include <stdint.h>

#define B_ 4
#define V_ 778
#define F_ 1538
#define S_ 320
#define TILE 16
#define NT 256
#define NW (NT / 32)
#define NSPLIT 4
#define SFACES ((F_ + NSPLIT - 1) / NSPLIT)   // 385

// Per (batch, face): 3 edges x (A', B', C', pad) with NEGATED scaled coeffs:
// dn = A'*px + B'*py + C' = -(dist/sigma)*log2(e);  t = exp2(dn) = exp(-dist/sigma).
__device__ float g_coeffs[B_ * F_ * 12];
// partial products per split: [split][b][y][x]
__device__ float g_part[NSPLIT * B_ * S_ * S_];

__global__ void precompute_kernel(const float* __restrict__ verts,
                                  const int* __restrict__ faces) {
    int idx = blockIdx.x * blockDim.x + threadIdx.x;
    if (idx >= B_ * F_) return;
    int b = idx / F_;
    int f = idx - b * F_;
    int i0 = faces[f * 3 + 0], i1 = faces[f * 3 + 1], i2 = faces[f * 3 + 2];
    const float* vb = verts + b * V_ * 3;
    float x0 = vb[i0 * 3 + 0], y0 = -vb[i0 * 3 + 1];
    float x1 = vb[i1 * 3 + 0], y1 = -vb[i1 * 3 + 1];
    float x2 = vb[i2 * 3 + 0], y2 = -vb[i2 * 3 + 1];
    float area2 = (x1 - x0) * (y2 - y0) - (y1 - y0) * (x2 - x0);
    float sgn = (area2 > 0.f) ? 1.f : ((area2 < 0.f) ? -1.f : 0.f);
    const float INVS = 1.4426950408889634f / 0.01f;  // log2(e)/SIGMA

    float ax[3] = {x0, x1, x2}, ay[3] = {y0, y1, y2};
    float bx[3] = {x1, x2, x0}, by[3] = {y1, y2, y0};
    float* o = g_coeffs + idx * 12;
#pragma unroll
    for (int e = 0; e < 3; e++) {
        float ex = bx[e] - ax[e];
        float ey = by[e] - ay[e];
        float inv_len = 1.0f / (sqrtf(ex * ex + ey * ey) + 1e-8f);
        float k = sgn * inv_len * INVS;
        // negated coefficients
        o[e * 4 + 0] = k * ey;
        o[e * 4 + 1] = -k * ex;
        o[e * 4 + 2] = k * (ex * ay[e] - ey * ax[e]);
        o[e * 4 + 3] = 0.f;
    }
}

__device__ __forceinline__ float ex2f(float x) {
    float r; asm("ex2.approx.ftz.f32 %0, %1;" : "=f"(r) : "f"(x)); return r;
}
__device__ __forceinline__ float rcpf(float x) {
    float r; asm("rcp.approx.ftz.f32 %0, %1;" : "=f"(r) : "f"(x)); return r;
}

__global__ __launch_bounds__(NT) void silhouette_kernel() {
    __shared__ float4 s_face[NT * 3];   // compacted (e0,e1,e2) per active face
    __shared__ int s_wcnt[NW];
    __shared__ int s_wbase[NW];
    __shared__ int s_total;
    __shared__ int s_deep;

    const int tid = threadIdx.x;
    const int w = tid >> 5;
    const int lane = tid & 31;
    const int bz = blockIdx.z;          // b*NSPLIT + split
    const int b = bz >> 2;
    const int split = bz & 3;
    const int x0 = blockIdx.x * TILE;
    const int y0 = blockIdx.y * TILE;

    if (tid == 0) s_deep = 0;
    __syncthreads();

    // thresholds on dn = -(dist/sigma)*log2(e)
    const float L = 10.098865f;        // 7*log2e : live if max(dn) < L
    const float DPN = -21.6404256f;    // -15*log2e : dn < DPN means edge deep
    const float STEP = 2.0f / S_;

    const float cx = (x0 + 8.0f) * STEP - 1.0f;
    const float cy = (y0 + 8.0f) * STEP - 1.0f;
    const float hx = 7.5f * STEP + 1e-4f;
    const float hy = hx;

    const int pxi = x0 + (tid & 15);
    const int pyi = y0 + (tid >> 4);
    const float px = (pxi + 0.5f) * STEP - 1.0f;
    const float py = (pyi + 0.5f) * STEP - 1.0f;

    const float RMIN = 1.0f - (1.0f - 1e-6f);   // exact fp32 clip residue
    float W = 1.0f;

    const float* cb = g_coeffs + (size_t)b * F_ * 12;
    const int fLo = split * SFACES;
    const int fHi = min(fLo + SFACES, F_);

    for (int base = fLo; base < fHi; base += NT) {
        // ---- cull: one face per thread ----
        int f = base + tid;
        bool active = false, deep = false;
        float4 e0, e1, e2;
        if (f < fHi) {
            const float4* cp = (const float4*)(cb + (size_t)f * 12);
            e0 = __ldg(cp); e1 = __ldg(cp + 1); e2 = __ldg(cp + 2);
            float n0 = fmaf(e0.x, cx, fmaf(e0.y, cy, e0.z));
            float n1 = fmaf(e1.x, cx, fmaf(e1.y, cy, e1.z));
            float n2 = fmaf(e2.x, cx, fmaf(e2.y, cy, e2.z));
            float x0e = fmaf(fabsf(e0.x), hx, fabsf(e0.y) * hy);
            float x1e = fmaf(fabsf(e1.x), hx, fabsf(e1.y) * hy);
            float x2e = fmaf(fabsf(e2.x), hx, fabsf(e2.y) * hy);
            // dead: whole tile beyond L on some edge (dn - ext > L)
            bool dead = (n0 - x0e > L) || (n1 - x1e > L) || (n2 - x2e > L);
            // deep: whole tile deep inside all edges (dn + ext < DPN)
            deep = (n0 + x0e < DPN) && (n1 + x1e < DPN) && (n2 + x2e < DPN);
            active = !dead && !deep;
        }
        unsigned balA = __ballot_sync(0xffffffffu, active);
        unsigned balD = __ballot_sync(0xffffffffu, deep);
        if (lane == 0) {
            s_wcnt[w] = __popc(balA);
            if (balD) atomicAdd(&s_deep, __popc(balD));
        }
        __syncthreads();
        if (tid == 0) {   // deterministic exclusive scan
            int acc = 0;
#pragma unroll
            for (int i = 0; i < NW; i++) { s_wbase[i] = acc; acc += s_wcnt[i]; }
            s_total = acc;
        }
        __syncthreads();
        if (active) {
            int pos = s_wbase[w] + __popc(balA & ((1u << lane) - 1u));
            s_face[pos * 3 + 0] = e0;
            s_face[pos * 3 + 1] = e1;
            s_face[pos * 3 + 2] = e2;
        }
        __syncthreads();

        // ---- eval: one pixel per thread over compacted faces ----
        const int n = s_total;
        const float4* sp_ = s_face;
#pragma unroll 2
        for (int j = 0; j < n; j++, sp_ += 3) {
            float4 f0 = sp_[0];
            float4 f1 = sp_[1];
            float4 f2 = sp_[2];
            float dn0 = fmaf(f0.x, px, fmaf(f0.y, py, f0.z));
            float dn1 = fmaf(f1.x, px, fmaf(f1.y, py, f1.z));
            float dn2 = fmaf(f2.x, px, fmaf(f2.y, py, f2.z));
            float mx01 = fmaxf(dn0, dn1);
            float m = fmaxf(mx01, dn2);
            if (m < L) {
                float r;
                if (m < DPN) {
                    r = RMIN;                       // all edges deep: clipped const
                } else {
                    float mn01 = fminf(dn0, dn1);
                    float mid = fmaxf(mn01, fminf(mx01, dn2));
                    if (mid < DPN) {
                        float t = ex2f(m);          // single relevant edge
                        r = fmaxf(t * rcpf(1.0f + t), RMIN);
                    } else {
                        float t0 = ex2f(dn0);
                        float t1 = ex2f(dn1);
                        float t2 = ex2f(dn2);
                        float sA = t1 + t2;
                        float pA = t1 * t2;
                        float sp = sA + pA;
                        float Q = fmaf(t0, sp, t0 + sp);
                        r = fmaxf(Q * rcpf(1.0f + Q), RMIN);
                    }
                }
                W *= r;
            }
        }
        __syncthreads();   // protect s_face
    }

    // fold deep faces of this split: exact clipped constant per face
    int nd = s_deep;
    if (nd >= 8) {
        W = 0.0f;
    } else {
        for (int i = 0; i < nd; i++) W *= RMIN;
    }

    g_part[(((size_t)split * B_ + b) * S_ + pyi) * S_ + pxi] = W;
}

__global__ __launch_bounds__(256) void combine_kernel(float* __restrict__ out) {
    int i = blockIdx.x * blockDim.x + threadIdx.x;
    if (i >= B_ * S_ * S_) return;
    const int STRIDE = B_ * S_ * S_;
    float w0 = g_part[i];
    float w1 = g_part[STRIDE + i];
    float w2 = g_part[2 * STRIDE + i];
    float w3 = g_part[3 * STRIDE + i];
    out[i] = 1.0f - (w0 * w1) * (w2 * w3);
}

extern "C" void kernel_launch(void* const* d_in, const int* in_sizes, int n_in,
                              void* d_out, int out_size) {
    const float* verts = (const float*)d_in[0];
    const int* faces = (const int*)d_in[1];
    float* out = (float*)d_out;

    int total = B_ * F_;
    precompute_kernel<<<(total + 255) / 256, 256>>>(verts, faces);

    dim3 grid(S_ / TILE, S_ / TILE, B_ * NSPLIT);
    silhouette_kernel<<<grid, NT>>>();

    int npix = B_ * S_ * S_;
    combine_kernel<<<(npix + 255) / 256, 256>>>(out);
}

// round 8
// speedup vs baseline: 2.1388x; 1.0796x over previous
#include <cuda_runtime.h>
#include <stdint.h>

#define B_ 4
#define V_ 778
#define F_ 1538
#define S_ 320
#define TILE 16
#define NT 256
#define NW (NT / 32)
#define NSPLIT 8
#define SFACES ((F_ + NSPLIT - 1) / NSPLIT)   // 193 <= NT : single cull chunk

// Per (batch, face): 3 edges x (A', B', C', pad) with NEGATED scaled coeffs:
// dn = A'*px + B'*py + C' = -(dist/sigma)*log2(e);  t = exp2(dn) = exp(-dist/sigma).
__device__ float g_coeffs[B_ * F_ * 12];
// partial products per split: [split][b][y][x]
__device__ float g_part[NSPLIT * B_ * S_ * S_];

__global__ void precompute_kernel(const float* __restrict__ verts,
                                  const int* __restrict__ faces) {
    int idx = blockIdx.x * blockDim.x + threadIdx.x;
    if (idx >= B_ * F_) return;
    int b = idx / F_;
    int f = idx - b * F_;
    int i0 = faces[f * 3 + 0], i1 = faces[f * 3 + 1], i2 = faces[f * 3 + 2];
    const float* vb = verts + b * V_ * 3;
    float x0 = vb[i0 * 3 + 0], y0 = -vb[i0 * 3 + 1];
    float x1 = vb[i1 * 3 + 0], y1 = -vb[i1 * 3 + 1];
    float x2 = vb[i2 * 3 + 0], y2 = -vb[i2 * 3 + 1];
    float area2 = (x1 - x0) * (y2 - y0) - (y1 - y0) * (x2 - x0);
    float sgn = (area2 > 0.f) ? 1.f : ((area2 < 0.f) ? -1.f : 0.f);
    const float INVS = 1.4426950408889634f / 0.01f;  // log2(e)/SIGMA

    float ax[3] = {x0, x1, x2}, ay[3] = {y0, y1, y2};
    float bx[3] = {x1, x2, x0}, by[3] = {y1, y2, y0};
    float* o = g_coeffs + idx * 12;
#pragma unroll
    for (int e = 0; e < 3; e++) {
        float ex = bx[e] - ax[e];
        float ey = by[e] - ay[e];
        float inv_len = 1.0f / (sqrtf(ex * ex + ey * ey) + 1e-8f);
        float k = sgn * inv_len * INVS;
        // negated coefficients
        o[e * 4 + 0] = k * ey;
        o[e * 4 + 1] = -k * ex;
        o[e * 4 + 2] = k * (ex * ay[e] - ey * ax[e]);
        o[e * 4 + 3] = 0.f;
    }
}

__device__ __forceinline__ float ex2f(float x) {
    float r; asm("ex2.approx.ftz.f32 %0, %1;" : "=f"(r) : "f"(x)); return r;
}
__device__ __forceinline__ float rcpf(float x) {
    float r; asm("rcp.approx.ftz.f32 %0, %1;" : "=f"(r) : "f"(x)); return r;
}

__global__ __launch_bounds__(NT) void silhouette_kernel() {
    __shared__ float4 s_face[SFACES * 3];   // compacted (e0,e1,e2) per active face
    __shared__ int s_wcnt[NW];
    __shared__ int s_wbase[NW];
    __shared__ int s_total;
    __shared__ int s_deep;

    const int tid = threadIdx.x;
    const int w = tid >> 5;
    const int lane = tid & 31;
    const int bz = blockIdx.z;          // b*NSPLIT + split
    const int b = bz >> 3;
    const int split = bz & 7;
    const int x0 = blockIdx.x * TILE;
    const int y0 = blockIdx.y * TILE;

    // thresholds on dn = -(dist/sigma)*log2(e)
    const float L = 9.3775173f;        // 6.5*log2e : live if max(dn) < L
    const float DPN = -21.6404256f;    // -15*log2e : dn < DPN means edge deep
    const float STEP = 2.0f / S_;

    const float cx = (x0 + 8.0f) * STEP - 1.0f;
    const float cy = (y0 + 8.0f) * STEP - 1.0f;
    const float hx = 7.5f * STEP + 1e-4f;
    const float hy = hx;

    const int pxi = x0 + (tid & 15);
    const int pyi = y0 + (tid >> 4);
    const float px = (pxi + 0.5f) * STEP - 1.0f;
    const float py = (pyi + 0.5f) * STEP - 1.0f;

    const float RMIN = 1.0f - (1.0f - 1e-6f);   // exact fp32 clip residue
    float W = 1.0f;

    const float* cb = g_coeffs + (size_t)b * F_ * 12;
    const int fLo = split * SFACES;
    const int fHi = min(fLo + SFACES, F_);

    // ---- cull (single chunk: SFACES <= NT): one face per thread ----
    {
        int f = fLo + tid;
        bool active = false, deep = false;
        float4 e0, e1, e2;
        if (f < fHi) {
            const float4* cp = (const float4*)(cb + (size_t)f * 12);
            e0 = __ldg(cp); e1 = __ldg(cp + 1); e2 = __ldg(cp + 2);
            float n0 = fmaf(e0.x, cx, fmaf(e0.y, cy, e0.z));
            float n1 = fmaf(e1.x, cx, fmaf(e1.y, cy, e1.z));
            float n2 = fmaf(e2.x, cx, fmaf(e2.y, cy, e2.z));
            float x0e = fmaf(fabsf(e0.x), hx, fabsf(e0.y) * hy);
            float x1e = fmaf(fabsf(e1.x), hx, fabsf(e1.y) * hy);
            float x2e = fmaf(fabsf(e2.x), hx, fabsf(e2.y) * hy);
            // dead: whole tile beyond L on some edge (dn - ext > L)
            bool dead = (n0 - x0e > L) || (n1 - x1e > L) || (n2 - x2e > L);
            // deep: whole tile deep inside all edges (dn + ext < DPN)
            deep = (n0 + x0e < DPN) && (n1 + x1e < DPN) && (n2 + x2e < DPN);
            active = !dead && !deep;
        }
        unsigned balA = __ballot_sync(0xffffffffu, active);
        unsigned balD = __ballot_sync(0xffffffffu, deep);
        if (lane == 0) {
            s_wcnt[w] = __popc(balA);
            if (w == 0) s_deep = 0;
        }
        __syncthreads();
        if (tid == 0) {   // deterministic exclusive scan + deep count
            int acc = 0;
#pragma unroll
            for (int i = 0; i < NW; i++) { s_wbase[i] = acc; acc += s_wcnt[i]; }
            s_total = acc;
        }
        if (lane == 0 && balD) atomicAdd(&s_deep, __popc(balD));
        __syncthreads();
        if (active) {
            int pos = s_wbase[w] + __popc(balA & ((1u << lane) - 1u));
            s_face[pos * 3 + 0] = e0;
            s_face[pos * 3 + 1] = e1;
            s_face[pos * 3 + 2] = e2;
        }
        __syncthreads();
    }

    // ---- eval: one pixel per thread over compacted faces ----
    const int n = s_total;
    const float4* sp_ = s_face;
#pragma unroll 2
    for (int j = 0; j < n; j++, sp_ += 3) {
        float4 f0 = sp_[0];
        float4 f1 = sp_[1];
        float4 f2 = sp_[2];
        float dn0 = fmaf(f0.x, px, fmaf(f0.y, py, f0.z));
        float dn1 = fmaf(f1.x, px, fmaf(f1.y, py, f1.z));
        float dn2 = fmaf(f2.x, px, fmaf(f2.y, py, f2.z));
        float mx01 = fmaxf(dn0, dn1);
        float m = fmaxf(mx01, dn2);
        if (m < L) {
            float r;
            if (m < DPN) {
                r = RMIN;                       // all edges deep: clipped const
            } else {
                float mn01 = fminf(dn0, dn1);
                float mid = fmaxf(mn01, fminf(mx01, dn2));
                if (mid < DPN) {
                    float t = ex2f(m);          // single relevant edge
                    r = fmaxf(t * rcpf(1.0f + t), RMIN);
                } else {
                    float t0 = ex2f(dn0);
                    float t1 = ex2f(dn1);
                    float t2 = ex2f(dn2);
                    float sA = t1 + t2;
                    float pA = t1 * t2;
                    float sp = sA + pA;
                    float Q = fmaf(t0, sp, t0 + sp);
                    r = fmaxf(Q * rcpf(1.0f + Q), RMIN);
                }
            }
            W *= r;
        }
    }

    // fold deep faces of this split: exact clipped constant per face
    int nd = s_deep;
    if (nd >= 8) {
        W = 0.0f;
    } else {
        for (int i = 0; i < nd; i++) W *= RMIN;
    }

    g_part[(((size_t)split * B_ + b) * S_ + pyi) * S_ + pxi] = W;
}

__global__ __launch_bounds__(256) void combine_kernel(float* __restrict__ out) {
    int i = blockIdx.x * blockDim.x + threadIdx.x;
    if (i >= B_ * S_ * S_) return;
    const int STRIDE = B_ * S_ * S_;
    float w = g_part[i];
#pragma unroll
    for (int s = 1; s < NSPLIT; s++) w *= g_part[s * STRIDE + i];
    out[i] = 1.0f - w;
}

extern "C" void kernel_launch(void* const* d_in, const int* in_sizes, int n_in,
                              void* d_out, int out_size) {
    const float* verts = (const float*)d_in[0];
    const int* faces = (const int*)d_in[1];
    float* out = (float*)d_out;

    int total = B_ * F_;
    precompute_kernel<<<(total + 255) / 256, 256>>>(verts, faces);

    dim3 grid(S_ / TILE, S_ / TILE, B_ * NSPLIT);
    silhouette_kernel<<<grid, NT>>>();

    int npix = B_ * S_ * S_;
    combine_kernel<<<(npix + 255) / 256, 256>>>(out);
}

// round 9
// speedup vs baseline: 2.1701x; 1.0147x over previous
#include <cuda_runtime.h>
#include <stdint.h>

#define B_ 4
#define V_ 778
#define F_ 1538
#define S_ 320
#define TILE 16
#define NT 256
#define NW (NT / 32)
#define NSPLIT 16
#define SFACES ((F_ + NSPLIT - 1) / NSPLIT)   // 97 <= NT : single cull chunk

// Per (batch, face): 3 edges x (A', B', C', pad) with NEGATED scaled coeffs:
// dn = A'*px + B'*py + C' = -(dist/sigma)*log2(e);  t = exp2(dn) = exp(-dist/sigma).
__device__ float g_coeffs[B_ * F_ * 12];
// partial products per split: [split][b][y][x]
__device__ float g_part[NSPLIT * B_ * S_ * S_];

__global__ void precompute_kernel(const float* __restrict__ verts,
                                  const int* __restrict__ faces) {
    int idx = blockIdx.x * blockDim.x + threadIdx.x;
    if (idx >= B_ * F_) return;
    int b = idx / F_;
    int f = idx - b * F_;
    int i0 = faces[f * 3 + 0], i1 = faces[f * 3 + 1], i2 = faces[f * 3 + 2];
    const float* vb = verts + b * V_ * 3;
    float x0 = vb[i0 * 3 + 0], y0 = -vb[i0 * 3 + 1];
    float x1 = vb[i1 * 3 + 0], y1 = -vb[i1 * 3 + 1];
    float x2 = vb[i2 * 3 + 0], y2 = -vb[i2 * 3 + 1];
    float area2 = (x1 - x0) * (y2 - y0) - (y1 - y0) * (x2 - x0);
    float sgn = (area2 > 0.f) ? 1.f : ((area2 < 0.f) ? -1.f : 0.f);
    const float INVS = 1.4426950408889634f / 0.01f;  // log2(e)/SIGMA

    float ax[3] = {x0, x1, x2}, ay[3] = {y0, y1, y2};
    float bx[3] = {x1, x2, x0}, by[3] = {y1, y2, y0};
    float* o = g_coeffs + idx * 12;
#pragma unroll
    for (int e = 0; e < 3; e++) {
        float ex = bx[e] - ax[e];
        float ey = by[e] - ay[e];
        float inv_len = 1.0f / (sqrtf(ex * ex + ey * ey) + 1e-8f);
        float k = sgn * inv_len * INVS;
        // negated coefficients
        o[e * 4 + 0] = k * ey;
        o[e * 4 + 1] = -k * ex;
        o[e * 4 + 2] = k * (ex * ay[e] - ey * ax[e]);
        o[e * 4 + 3] = 0.f;
    }
}

__device__ __forceinline__ float ex2f(float x) {
    float r; asm("ex2.approx.ftz.f32 %0, %1;" : "=f"(r) : "f"(x)); return r;
}
__device__ __forceinline__ float rcpf(float x) {
    float r; asm("rcp.approx.ftz.f32 %0, %1;" : "=f"(r) : "f"(x)); return r;
}

__global__ __launch_bounds__(NT) void silhouette_kernel() {
    __shared__ float4 s_face[SFACES * 3];   // compacted (e0,e1,e2) per active face
    __shared__ int s_wcnt[NW];
    __shared__ int s_wbase[NW];
    __shared__ int s_total;
    __shared__ int s_deep;

    const int tid = threadIdx.x;
    const int w = tid >> 5;
    const int lane = tid & 31;
    const int bz = blockIdx.z;          // b*NSPLIT + split
    const int b = bz >> 4;
    const int split = bz & 15;
    const int x0 = blockIdx.x * TILE;
    const int y0 = blockIdx.y * TILE;

    // thresholds on dn = -(dist/sigma)*log2(e)
    const float L = 8.6561702f;        // 6*log2e : live if max(dn) < L
    const float DPN = -21.6404256f;    // -15*log2e : dn < DPN means edge deep
    const float STEP = 2.0f / S_;

    const float cx = (x0 + 8.0f) * STEP - 1.0f;
    const float cy = (y0 + 8.0f) * STEP - 1.0f;
    const float hx = 7.5f * STEP + 1e-4f;
    const float hy = hx;

    const int pxi = x0 + (tid & 15);
    const int pyi = y0 + (tid >> 4);
    const float px = (pxi + 0.5f) * STEP - 1.0f;
    const float py = (pyi + 0.5f) * STEP - 1.0f;

    const float RMIN = 1.0f - (1.0f - 1e-6f);   // exact fp32 clip residue
    float W = 1.0f;

    const float* cb = g_coeffs + (size_t)b * F_ * 12;
    const int fLo = split * SFACES;
    const int fHi = min(fLo + SFACES, F_);

    // ---- cull (single chunk: SFACES <= NT): one face per thread ----
    {
        int f = fLo + tid;
        bool active = false, deep = false;
        float4 e0, e1, e2;
        if (f < fHi) {
            const float4* cp = (const float4*)(cb + (size_t)f * 12);
            e0 = __ldg(cp); e1 = __ldg(cp + 1); e2 = __ldg(cp + 2);
            float n0 = fmaf(e0.x, cx, fmaf(e0.y, cy, e0.z));
            float n1 = fmaf(e1.x, cx, fmaf(e1.y, cy, e1.z));
            float n2 = fmaf(e2.x, cx, fmaf(e2.y, cy, e2.z));
            float x0e = fmaf(fabsf(e0.x), hx, fabsf(e0.y) * hy);
            float x1e = fmaf(fabsf(e1.x), hx, fabsf(e1.y) * hy);
            float x2e = fmaf(fabsf(e2.x), hx, fabsf(e2.y) * hy);
            // dead: whole tile beyond L on some edge (dn - ext > L)
            bool dead = (n0 - x0e > L) || (n1 - x1e > L) || (n2 - x2e > L);
            // deep: whole tile deep inside all edges (dn + ext < DPN)
            deep = (n0 + x0e < DPN) && (n1 + x1e < DPN) && (n2 + x2e < DPN);
            active = !dead && !deep;
        }
        unsigned balA = __ballot_sync(0xffffffffu, active);
        unsigned balD = __ballot_sync(0xffffffffu, deep);
        if (lane == 0) {
            s_wcnt[w] = __popc(balA);
            if (w == 0) s_deep = 0;
        }
        __syncthreads();
        if (tid == 0) {   // deterministic exclusive scan
            int acc = 0;
#pragma unroll
            for (int i = 0; i < NW; i++) { s_wbase[i] = acc; acc += s_wcnt[i]; }
            s_total = acc;
        }
        if (lane == 0 && balD) atomicAdd(&s_deep, __popc(balD));
        __syncthreads();
        if (active) {
            int pos = s_wbase[w] + __popc(balA & ((1u << lane) - 1u));
            s_face[pos * 3 + 0] = e0;
            s_face[pos * 3 + 1] = e1;
            s_face[pos * 3 + 2] = e2;
        }
        __syncthreads();
    }

    // ---- eval: one pixel per thread over compacted faces ----
    const int n = s_total;
    const float4* sp_ = s_face;
#pragma unroll 4
    for (int j = 0; j < n; j++, sp_ += 3) {
        float4 f0 = sp_[0];
        float4 f1 = sp_[1];
        float4 f2 = sp_[2];
        float dn0 = fmaf(f0.x, px, fmaf(f0.y, py, f0.z));
        float dn1 = fmaf(f1.x, px, fmaf(f1.y, py, f1.z));
        float dn2 = fmaf(f2.x, px, fmaf(f2.y, py, f2.z));
        float mx01 = fmaxf(dn0, dn1);
        float m = fmaxf(mx01, dn2);
        if (m < L) {
            float r;
            if (m < DPN) {
                r = RMIN;                       // all edges deep: clipped const
            } else {
                float mn01 = fminf(dn0, dn1);
                float mid = fmaxf(mn01, fminf(mx01, dn2));
                if (mid < DPN) {
                    float t = ex2f(m);          // single relevant edge
                    r = fmaxf(t * rcpf(1.0f + t), RMIN);
                } else {
                    float t0 = ex2f(dn0);
                    float t1 = ex2f(dn1);
                    float t2 = ex2f(dn2);
                    float sA = t1 + t2;
                    float pA = t1 * t2;
                    float sp = sA + pA;
                    float Q = fmaf(t0, sp, t0 + sp);
                    r = fmaxf(Q * rcpf(1.0f + Q), RMIN);
                }
            }
            W *= r;
        }
    }

    // fold deep faces of this split: exact clipped constant per face
    int nd = s_deep;
    if (nd >= 8) {
        W = 0.0f;
    } else {
        for (int i = 0; i < nd; i++) W *= RMIN;
    }

    g_part[(((size_t)split * B_ + b) * S_ + pyi) * S_ + pxi] = W;
}

__global__ __launch_bounds__(256) void combine_kernel(float* __restrict__ out) {
    int i = blockIdx.x * blockDim.x + threadIdx.x;
    if (i >= B_ * S_ * S_) return;
    const int STRIDE = B_ * S_ * S_;
    float w = g_part[i];
#pragma unroll
    for (int s = 1; s < NSPLIT; s++) w *= g_part[s * STRIDE + i];
    out[i] = 1.0f - w;
}

extern "C" void kernel_launch(void* const* d_in, const int* in_sizes, int n_in,
                              void* d_out, int out_size) {
    const float* verts = (const float*)d_in[0];
    const int* faces = (const int*)d_in[1];
    float* out = (float*)d_out;

    int total = B_ * F_;
    precompute_kernel<<<(total + 255) / 256, 256>>>(verts, faces);

    dim3 grid(S_ / TILE, S_ / TILE, B_ * NSPLIT);
    silhouette_kernel<<<grid, NT>>>();

    int npix = B_ * S_ * S_;
    combine_kernel<<<(npix + 255) / 256, 256>>>(out);
}